// round 1
// baseline (speedup 1.0000x reference)
#include <cuda_runtime.h>
#include <cstdint>

// Problem constants (fixed by the reference: x(2,8192,1024), h(8192,1024), bias(1024))
#define NFFT   16384
#define LOGN   14
#define DIMB   2
#define DIML   8192
#define DIMD   1024
#define NTHREADS 512

// Scratch (device globals: allocation-free per harness rules)
__device__ float2 g_tw[NFFT];            // twiddles W_N^j = e^{-2*pi*i*j/N}
__device__ float2 g_H[(size_t)DIMD * NFFT]; // digit-reversed spectrum of h, per channel (134 MB)

__device__ __forceinline__ float2 cmul(float2 a, float2 b) {
    return make_float2(a.x * b.x - a.y * b.y, a.x * b.y + a.y * b.x);
}
// a * conj(b)
__device__ __forceinline__ float2 cmulj(float2 a, float2 b) {
    return make_float2(a.x * b.x + a.y * b.y, a.y * b.x - a.x * b.y);
}

__global__ void twiddle_kernel() {
    int j = blockIdx.x * blockDim.x + threadIdx.x;
    if (j < NFFT) {
        float s, c;
        sincospif(2.0f * (float)j / (float)NFFT, &s, &c);
        g_tw[j] = make_float2(c, -s);
    }
}

// ---------------------------------------------------------------------------
// Radix-4 DIF forward FFT in shared memory.
// Natural-order input -> digit-reversed output (fixed permutation P of the
// true DFT). Pointwise products in the P-domain are valid for convolution
// because X and H use the same P.
// Slot assignment per stage: A[q*4m + k*m + r] = DFT4_k * W_{4m}^{k*r}.
// ---------------------------------------------------------------------------
__device__ void fft_fwd(float2* A) {
    #pragma unroll
    for (int lgm = LOGN - 2; lgm >= 0; lgm -= 2) {
        const int m    = 1 << lgm;
        const int step = NFFT >> (lgm + 2);
        #pragma unroll 2
        for (int t = threadIdx.x; t < NFFT / 4; t += NTHREADS) {
            const int r  = t & (m - 1);
            const int q  = t >> lgm;
            const int i0 = (q << (lgm + 2)) + r;
            float2 a = A[i0], b = A[i0 + m], c = A[i0 + 2 * m], d = A[i0 + 3 * m];
            float2 t0 = make_float2(a.x + c.x, a.y + c.y);
            float2 t1 = make_float2(a.x - c.x, a.y - c.y);
            float2 t2 = make_float2(b.x + d.x, b.y + d.y);
            float2 t3 = make_float2(b.x - d.x, b.y - d.y);
            float2 X0 = make_float2(t0.x + t2.x, t0.y + t2.y);
            float2 X1 = make_float2(t1.x + t3.y, t1.y - t3.x);  // t1 - i*t3
            float2 X2 = make_float2(t0.x - t2.x, t0.y - t2.y);
            float2 X3 = make_float2(t1.x - t3.y, t1.y + t3.x);  // t1 + i*t3
            const int rs = r * step;
            A[i0]         = X0;
            A[i0 + m]     = cmul(X1, __ldg(&g_tw[rs]));
            A[i0 + 2 * m] = cmul(X2, __ldg(&g_tw[2 * rs]));
            A[i0 + 3 * m] = cmul(X3, __ldg(&g_tw[3 * rs]));
        }
        __syncthreads();
    }
}

// ---------------------------------------------------------------------------
// Radix-4 DIT inverse: exact algebraic inverse of fft_fwd stage-by-stage in
// reverse order (un-twiddle with conj, then unnormalized inverse-DFT4).
// Digit-reversed input -> natural output, scaled by NFFT (caller divides).
// ---------------------------------------------------------------------------
__device__ void fft_inv(float2* A) {
    #pragma unroll
    for (int lgm = 0; lgm <= LOGN - 2; lgm += 2) {
        const int m    = 1 << lgm;
        const int step = NFFT >> (lgm + 2);
        #pragma unroll 2
        for (int t = threadIdx.x; t < NFFT / 4; t += NTHREADS) {
            const int r  = t & (m - 1);
            const int q  = t >> lgm;
            const int i0 = (q << (lgm + 2)) + r;
            const int rs = r * step;
            float2 X0 = A[i0];
            float2 X1 = cmulj(A[i0 + m],     __ldg(&g_tw[rs]));
            float2 X2 = cmulj(A[i0 + 2 * m], __ldg(&g_tw[2 * rs]));
            float2 X3 = cmulj(A[i0 + 3 * m], __ldg(&g_tw[3 * rs]));
            float2 u0 = make_float2(X0.x + X2.x, X0.y + X2.y);
            float2 u1 = make_float2(X0.x - X2.x, X0.y - X2.y);
            float2 u2 = make_float2(X1.x + X3.x, X1.y + X3.y);
            float2 u3 = make_float2(X1.x - X3.x, X1.y - X3.y);
            float2 av = make_float2(u0.x + u2.x, u0.y + u2.y);           // X0+X1+X2+X3
            float2 cv = make_float2(u0.x - u2.x, u0.y - u2.y);           // X0-X1+X2-X3
            float2 bv = make_float2(u1.x - u3.y, u1.y + u3.x);           // u1 + i*u3
            float2 dv = make_float2(u1.x + u3.y, u1.y - u3.x);           // u1 - i*u3
            A[i0]         = av;
            A[i0 + m]     = bv;
            A[i0 + 2 * m] = cv;
            A[i0 + 3 * m] = dv;
        }
        __syncthreads();
    }
}

// ---------------------------------------------------------------------------
// Kernel 1: spectrum of h, one CTA per channel d.
// ---------------------------------------------------------------------------
__global__ __launch_bounds__(NTHREADS)
void fft_h_kernel(const float* __restrict__ h) {
    extern __shared__ float2 sA[];
    const int d = blockIdx.x;
    for (int n = threadIdx.x; n < NFFT; n += NTHREADS) {
        float v = (n < DIML) ? h[(size_t)n * DIMD + d] : 0.0f;
        sA[n] = make_float2(v, 0.0f);
    }
    __syncthreads();
    fft_fwd(sA);  // ends with __syncthreads
    float2* Hd = g_H + (size_t)d * NFFT;
    for (int p = threadIdx.x; p < NFFT; p += NTHREADS)
        Hd[p] = sA[p];
}

// ---------------------------------------------------------------------------
// Kernel 2: forward FFT of x, multiply by H, inverse FFT, + bias.
// One CTA per (b, d).
// ---------------------------------------------------------------------------
__global__ __launch_bounds__(NTHREADS)
void fft_conv_kernel(const float* __restrict__ x,
                     const float* __restrict__ bias,
                     float* __restrict__ y) {
    extern __shared__ float2 sA[];
    const int bd = blockIdx.x;
    const int d  = bd & (DIMD - 1);
    const int b  = bd >> 10;

    const float* xp = x + (size_t)b * DIML * DIMD + d;
    for (int n = threadIdx.x; n < NFFT; n += NTHREADS) {
        float v = (n < DIML) ? xp[(size_t)n * DIMD] : 0.0f;
        sA[n] = make_float2(v, 0.0f);
    }
    __syncthreads();

    fft_fwd(sA);

    const float2* Hd = g_H + (size_t)d * NFFT;
    for (int p = threadIdx.x; p < NFFT; p += NTHREADS)
        sA[p] = cmul(sA[p], __ldg(&Hd[p]));
    __syncthreads();

    fft_inv(sA);

    const float bval  = __ldg(&bias[d]);
    const float scale = 1.0f / (float)NFFT;
    float* yp = y + (size_t)b * DIML * DIMD + d;
    for (int n = threadIdx.x; n < DIML; n += NTHREADS)
        yp[(size_t)n * DIMD] = fmaf(sA[n].x, scale, bval);
}

// ---------------------------------------------------------------------------
extern "C" void kernel_launch(void* const* d_in, const int* in_sizes, int n_in,
                              void* d_out, int out_size) {
    const float* x    = (const float*)d_in[0];  // (2, 8192, 1024) f32
    const float* h    = (const float*)d_in[1];  // (8192, 1024) f32
    const float* bias = (const float*)d_in[2];  // (1024,) f32
    float* y = (float*)d_out;                   // (2, 8192, 1024) f32

    const int smem = NFFT * sizeof(float2);     // 128 KB
    cudaFuncSetAttribute(fft_h_kernel,
                         cudaFuncAttributeMaxDynamicSharedMemorySize, smem);
    cudaFuncSetAttribute(fft_conv_kernel,
                         cudaFuncAttributeMaxDynamicSharedMemorySize, smem);

    twiddle_kernel<<<(NFFT + NTHREADS - 1) / NTHREADS, NTHREADS>>>();
    fft_h_kernel<<<DIMD, NTHREADS, smem>>>(h);
    fft_conv_kernel<<<DIMB * DIMD, NTHREADS, smem>>>(x, bias, y);
}

// round 2
// speedup vs baseline: 2.7459x; 2.7459x over previous
#include <cuda_runtime.h>
#include <cstdint>

#define NFFT   16384
#define LOGN   14
#define DIMB   2
#define DIML   8192
#define DIMD   1024
#define NTHREADS 512
#define NTW    5461   // sum of per-stage twiddle table sizes: 4096+1024+256+64+16+4+1

// Bank-conflict-killing XOR swizzle for the float2 data array.
// XORs bits[5:4] into bits[3:2] AND bits[1:0] (factor 5 = 0b101) — makes every
// radix-4 stage's 4-point access pattern hit 16 distinct banks per half-warp.
#define SWZ(i) ((i) ^ ((((i) >> 4) & 3) * 5))

// ---------------- device scratch (allocation-free) ----------------
__device__ float2 g_twst[NTW];                    // per-stage twiddle tables
__device__ float2 g_H [(size_t)DIMD * NFFT];      // spectrum of h (swizzled-digit-rev order)
__device__ float2 g_xt[(size_t)DIMD * DIML];      // transposed x, batches packed (x0,x1)
__device__ float  g_ht[(size_t)DIMD * DIML];      // transposed h
__device__ float2 g_ys[(size_t)DIMD * DIML];      // transposed scaled output (y0,y1)

__device__ __forceinline__ float2 cmul(float2 a, float2 b) {
    return make_float2(a.x * b.x - a.y * b.y, a.x * b.y + a.y * b.x);
}

// ---------------- twiddle init: per-stage tables ----------------
// stage si: lgm = 12-2si, m = 1<<lgm, entry r = W_N^{r * N/(4m)} = e^{-2*pi*i*r/(4m)}
__global__ void twiddle_kernel() {
    const int offs[7] = {0, 4096, 5120, 5376, 5440, 5456, 5460};
    int si  = blockIdx.y;
    int lgm = 12 - 2 * si;
    int m   = 1 << lgm;
    int r   = blockIdx.x * 256 + threadIdx.x;
    if (r < m) {
        float s, c;
        sincospif(0.5f * (float)r / (float)m, &s, &c);
        g_twst[offs[si] + r] = make_float2(c, -s);
    }
}

// ---------------- radix-4 DIF forward (natural -> digit-rev, swizzled) -----
__device__ __forceinline__ void fft_fwd(float2* A, const float2* tw) {
    const int offs[7] = {0, 4096, 5120, 5376, 5440, 5456, 5460};
    #pragma unroll
    for (int si = 0; si < 7; si++) {
        const int lgm = 12 - 2 * si;
        const int m   = 1 << lgm;
        const float2* twm = tw + offs[si];
        #pragma unroll 2
        for (int t = threadIdx.x; t < NFFT / 4; t += NTHREADS) {
            const int r  = t & (m - 1);
            const int q  = t >> lgm;
            const int i0 = (q << (lgm + 2)) + r;
            float2 a = A[SWZ(i0)], b = A[SWZ(i0 + m)];
            float2 c = A[SWZ(i0 + 2 * m)], d = A[SWZ(i0 + 3 * m)];
            float2 t0 = make_float2(a.x + c.x, a.y + c.y);
            float2 t1 = make_float2(a.x - c.x, a.y - c.y);
            float2 t2 = make_float2(b.x + d.x, b.y + d.y);
            float2 t3 = make_float2(b.x - d.x, b.y - d.y);
            float2 X0 = make_float2(t0.x + t2.x, t0.y + t2.y);
            float2 X1 = make_float2(t1.x + t3.y, t1.y - t3.x);
            float2 X2 = make_float2(t0.x - t2.x, t0.y - t2.y);
            float2 X3 = make_float2(t1.x - t3.y, t1.y + t3.x);
            float2 w1 = twm[r];
            float2 w2 = cmul(w1, w1);
            float2 w3 = cmul(w1, w2);
            A[SWZ(i0)]         = X0;
            A[SWZ(i0 + m)]     = cmul(X1, w1);
            A[SWZ(i0 + 2 * m)] = cmul(X2, w2);
            A[SWZ(i0 + 3 * m)] = cmul(X3, w3);
        }
        __syncthreads();
    }
}

// ---------------- radix-4 DIT inverse (digit-rev -> natural, unnormalized) --
__device__ __forceinline__ void fft_inv(float2* A, const float2* tw) {
    const int offs[7] = {0, 4096, 5120, 5376, 5440, 5456, 5460};
    #pragma unroll
    for (int si = 6; si >= 0; si--) {
        const int lgm = 12 - 2 * si;
        const int m   = 1 << lgm;
        const float2* twm = tw + offs[si];
        #pragma unroll 2
        for (int t = threadIdx.x; t < NFFT / 4; t += NTHREADS) {
            const int r  = t & (m - 1);
            const int q  = t >> lgm;
            const int i0 = (q << (lgm + 2)) + r;
            float2 w1 = twm[r];
            w1.y = -w1.y;                       // conj
            float2 w2 = cmul(w1, w1);
            float2 w3 = cmul(w1, w2);
            float2 X0 = A[SWZ(i0)];
            float2 X1 = cmul(A[SWZ(i0 + m)],     w1);
            float2 X2 = cmul(A[SWZ(i0 + 2 * m)], w2);
            float2 X3 = cmul(A[SWZ(i0 + 3 * m)], w3);
            float2 u0 = make_float2(X0.x + X2.x, X0.y + X2.y);
            float2 u1 = make_float2(X0.x - X2.x, X0.y - X2.y);
            float2 u2 = make_float2(X1.x + X3.x, X1.y + X3.y);
            float2 u3 = make_float2(X1.x - X3.x, X1.y - X3.y);
            A[SWZ(i0)]         = make_float2(u0.x + u2.x, u0.y + u2.y);
            A[SWZ(i0 + m)]     = make_float2(u1.x - u3.y, u1.y + u3.x);
            A[SWZ(i0 + 2 * m)] = make_float2(u0.x - u2.x, u0.y - u2.y);
            A[SWZ(i0 + 3 * m)] = make_float2(u1.x + u3.y, u1.y - u3.x);
        }
        __syncthreads();
    }
}

// ---------------- transposes -------------------------------------------
// x(2, L, D) -> g_xt[d][n] = (x[0,n,d], x[1,n,d])
__global__ __launch_bounds__(256)
void transpose_x_kernel(const float* __restrict__ x) {
    __shared__ float2 tile[32][33];
    const int d0 = blockIdx.x * 32, n0 = blockIdx.y * 32;
    for (int i = threadIdx.y; i < 32; i += 8) {
        const size_t base = (size_t)(n0 + i) * DIMD + d0 + threadIdx.x;
        tile[i][threadIdx.x] = make_float2(x[base], x[base + (size_t)DIML * DIMD]);
    }
    __syncthreads();
    for (int i = threadIdx.y; i < 32; i += 8)
        g_xt[(size_t)(d0 + i) * DIML + n0 + threadIdx.x] = tile[threadIdx.x][i];
}

// h(L, D) -> g_ht[d][n]
__global__ __launch_bounds__(256)
void transpose_h_kernel(const float* __restrict__ h) {
    __shared__ float tile[32][33];
    const int d0 = blockIdx.x * 32, n0 = blockIdx.y * 32;
    for (int i = threadIdx.y; i < 32; i += 8)
        tile[i][threadIdx.x] = h[(size_t)(n0 + i) * DIMD + d0 + threadIdx.x];
    __syncthreads();
    for (int i = threadIdx.y; i < 32; i += 8)
        g_ht[(size_t)(d0 + i) * DIML + n0 + threadIdx.x] = tile[threadIdx.x][i];
}

// g_ys[d][n] -> y[b][n][d] + bias[d]
__global__ __launch_bounds__(256)
void transpose_out_kernel(const float* __restrict__ bias, float* __restrict__ y) {
    __shared__ float2 tile[32][33];
    const int n0 = blockIdx.x * 32, d0 = blockIdx.y * 32;
    for (int i = threadIdx.y; i < 32; i += 8)
        tile[i][threadIdx.x] = g_ys[(size_t)(d0 + i) * DIML + n0 + threadIdx.x];
    __syncthreads();
    for (int i = threadIdx.y; i < 32; i += 8) {
        const int d = d0 + threadIdx.x;
        const int n = n0 + i;
        const float bv = __ldg(&bias[d]);
        const float2 v = tile[threadIdx.x][i];
        y[(size_t)n * DIMD + d]                       = v.x + bv;
        y[(size_t)(DIML + n) * DIMD + d]              = v.y + bv;
    }
}

// ---------------- FFT kernels -------------------------------------------
__global__ __launch_bounds__(NTHREADS)
void fft_h_kernel() {
    extern __shared__ float2 sm[];
    float2* sA = sm;
    float2* sT = sm + NFFT;
    const int d = blockIdx.x;
    for (int j = threadIdx.x; j < NTW; j += NTHREADS) sT[j] = g_twst[j];
    const float* hp = g_ht + (size_t)d * DIML;
    for (int n = threadIdx.x; n < NFFT; n += NTHREADS) {
        float v = (n < DIML) ? hp[n] : 0.0f;
        sA[SWZ(n)] = make_float2(v, 0.0f);
    }
    __syncthreads();
    fft_fwd(sA, sT);
    float2* Hd = g_H + (size_t)d * NFFT;
    for (int p = threadIdx.x; p < NFFT; p += NTHREADS)
        Hd[p] = sA[SWZ(p)];
}

__global__ __launch_bounds__(NTHREADS)
void fft_conv_kernel() {
    extern __shared__ float2 sm[];
    float2* sA = sm;
    float2* sT = sm + NFFT;
    const int d = blockIdx.x;
    for (int j = threadIdx.x; j < NTW; j += NTHREADS) sT[j] = g_twst[j];
    const float2* xp = g_xt + (size_t)d * DIML;
    for (int n = threadIdx.x; n < NFFT; n += NTHREADS) {
        float2 v = (n < DIML) ? xp[n] : make_float2(0.0f, 0.0f);
        sA[SWZ(n)] = v;            // z = x0 + i*x1 (batch packing)
    }
    __syncthreads();

    fft_fwd(sA, sT);

    const float2* Hd = g_H + (size_t)d * NFFT;
    for (int p = threadIdx.x; p < NFFT; p += NTHREADS)
        sA[SWZ(p)] = cmul(sA[SWZ(p)], __ldg(&Hd[p]));
    __syncthreads();

    fft_inv(sA, sT);

    const float scale = 1.0f / (float)NFFT;
    float2* yp = g_ys + (size_t)d * DIML;
    for (int n = threadIdx.x; n < DIML; n += NTHREADS) {
        float2 v = sA[SWZ(n)];
        yp[n] = make_float2(v.x * scale, v.y * scale);   // (y0, y1)
    }
}

// ---------------------------------------------------------------------------
extern "C" void kernel_launch(void* const* d_in, const int* in_sizes, int n_in,
                              void* d_out, int out_size) {
    const float* x    = (const float*)d_in[0];
    const float* h    = (const float*)d_in[1];
    const float* bias = (const float*)d_in[2];
    float* y = (float*)d_out;

    const int smem = (NFFT + NTW) * sizeof(float2);   // ~175 KB
    static bool attr_done = false;
    cudaFuncSetAttribute(fft_h_kernel,
                         cudaFuncAttributeMaxDynamicSharedMemorySize, smem);
    cudaFuncSetAttribute(fft_conv_kernel,
                         cudaFuncAttributeMaxDynamicSharedMemorySize, smem);
    (void)attr_done;

    twiddle_kernel<<<dim3(16, 7), 256>>>();
    transpose_x_kernel<<<dim3(DIMD / 32, DIML / 32), dim3(32, 8)>>>(x);
    transpose_h_kernel<<<dim3(DIMD / 32, DIML / 32), dim3(32, 8)>>>(h);
    fft_h_kernel<<<DIMD, NTHREADS, smem>>>();
    fft_conv_kernel<<<DIMD, NTHREADS, smem>>>();
    transpose_out_kernel<<<dim3(DIML / 32, DIMD / 32), dim3(32, 8)>>>(bias, y);
}

// round 3
// speedup vs baseline: 3.7470x; 1.3646x over previous
#include <cuda_runtime.h>
#include <cstdint>

#define NFFT 16384
#define DIML 8192
#define DIMD 1024
#define NT   1024

// per-stage twiddle table offsets in smem (float2 units)
#define OT4096 0
#define OT1024 4096
#define OT256  5120
#define OT64   5376
#define OT16   5440
#define OT4    5456
#define NTW    5460

// conflict-killing swizzle: XOR low 4 bits with bits[7:4] (self-inverse)
#define SWZ(i) ((i) ^ (((i) >> 4) & 15))

// ---------------- device scratch ----------------
__device__ float2 g_twst[NTW];
__device__ float4 g_H [(size_t)DIMD * NFFT / 2];   // spectrum of h, pass-D layout
__device__ float2 g_xt[(size_t)DIMD * DIML];       // transposed x, batches packed
__device__ float  g_ht[(size_t)DIMD * DIML];       // transposed h
__device__ float2 g_ys[(size_t)DIMD * DIML];       // transposed scaled output

__device__ __forceinline__ float2 cmul(float2 a, float2 b) {
    return make_float2(a.x * b.x - a.y * b.y, a.x * b.y + a.y * b.x);
}
__device__ __forceinline__ float2 cadd(float2 a, float2 b) { return make_float2(a.x + b.x, a.y + b.y); }
__device__ __forceinline__ float2 csub(float2 a, float2 b) { return make_float2(a.x - b.x, a.y - b.y); }

// DIF forward radix-4 butterfly (in place)
__device__ __forceinline__ void bfly(float2& a, float2& b, float2& c, float2& d) {
    float2 t0 = cadd(a, c), t1 = csub(a, c), t2 = cadd(b, d), t3 = csub(b, d);
    a = cadd(t0, t2);
    b = make_float2(t1.x + t3.y, t1.y - t3.x);
    c = csub(t0, t2);
    d = make_float2(t1.x - t3.y, t1.y + t3.x);
}
// inverse radix-4 butterfly (unnormalized)
__device__ __forceinline__ void ibfly(float2& a, float2& b, float2& c, float2& d) {
    float2 u0 = cadd(a, c), u1 = csub(a, c), u2 = cadd(b, d), u3 = csub(b, d);
    a = cadd(u0, u2);
    b = make_float2(u1.x - u3.y, u1.y + u3.x);
    c = csub(u0, u2);
    d = make_float2(u1.x + u3.y, u1.y - u3.x);
}
// apply w, w^2, w^3 to outputs 1..3
__device__ __forceinline__ void tw3(float2& b, float2& c, float2& d, float2 w) {
    float2 w2 = cmul(w, w), w3 = cmul(w, w2);
    b = cmul(b, w); c = cmul(c, w2); d = cmul(d, w3);
}
// apply conj(w)^{1..3}
__device__ __forceinline__ void itw3(float2& b, float2& c, float2& d, float2 w) {
    float2 wc = make_float2(w.x, -w.y);
    float2 w2 = cmul(wc, wc), w3 = cmul(wc, w2);
    b = cmul(b, wc); c = cmul(c, w2); d = cmul(d, w3);
}

// ---------------- twiddle init ----------------
__global__ void twiddle_kernel() {
    const int offs[6] = {OT4096, OT1024, OT256, OT64, OT16, OT4};
    const int ms[6]   = {4096, 1024, 256, 64, 16, 4};
    int si = blockIdx.y;
    int m  = ms[si];
    int r  = blockIdx.x * 256 + threadIdx.x;
    if (r < m) {
        float s, c;
        sincospif(0.5f * (float)r / (float)m, &s, &c);
        g_twst[offs[si] + r] = make_float2(c, -s);
    }
}

// ---------------- transposes ----------------
__global__ __launch_bounds__(256)
void transpose_x_kernel(const float* __restrict__ x) {
    __shared__ float2 tile[32][33];
    const int d0 = blockIdx.x * 32, n0 = blockIdx.y * 32;
    for (int i = threadIdx.y; i < 32; i += 8) {
        const size_t base = (size_t)(n0 + i) * DIMD + d0 + threadIdx.x;
        tile[i][threadIdx.x] = make_float2(x[base], x[base + (size_t)DIML * DIMD]);
    }
    __syncthreads();
    for (int i = threadIdx.y; i < 32; i += 8)
        g_xt[(size_t)(d0 + i) * DIML + n0 + threadIdx.x] = tile[threadIdx.x][i];
}

__global__ __launch_bounds__(256)
void transpose_h_kernel(const float* __restrict__ h) {
    __shared__ float tile[32][33];
    const int d0 = blockIdx.x * 32, n0 = blockIdx.y * 32;
    for (int i = threadIdx.y; i < 32; i += 8)
        tile[i][threadIdx.x] = h[(size_t)(n0 + i) * DIMD + d0 + threadIdx.x];
    __syncthreads();
    for (int i = threadIdx.y; i < 32; i += 8)
        g_ht[(size_t)(d0 + i) * DIML + n0 + threadIdx.x] = tile[threadIdx.x][i];
}

__global__ __launch_bounds__(256)
void transpose_out_kernel(const float* __restrict__ bias, float* __restrict__ y) {
    __shared__ float2 tile[32][33];
    const int n0 = blockIdx.x * 32, d0 = blockIdx.y * 32;
    for (int i = threadIdx.y; i < 32; i += 8)
        tile[i][threadIdx.x] = g_ys[(size_t)(d0 + i) * DIML + n0 + threadIdx.x];
    __syncthreads();
    for (int i = threadIdx.y; i < 32; i += 8) {
        const int d = d0 + threadIdx.x;
        const int n = n0 + i;
        const float bv = __ldg(&bias[d]);
        const float2 v = tile[threadIdx.x][i];
        y[(size_t)n * DIMD + d]          = v.x + bv;
        y[(size_t)(DIML + n) * DIMD + d] = v.y + bv;
    }
}

// ================= forward pass helpers (shared by both FFT kernels) ========

// Pass A butterflies: stages m=4096, m=1024 on v[a][b] (element t+1024b+4096a)
__device__ __forceinline__ void passA_fwd(float2 v[4][4], const float2* sT, int t) {
    #pragma unroll
    for (int b = 0; b < 4; b++) {
        bfly(v[0][b], v[1][b], v[2][b], v[3][b]);
        tw3(v[1][b], v[2][b], v[3][b], sT[OT4096 + t + 1024 * b]);
    }
    float2 w = sT[OT1024 + t];
    #pragma unroll
    for (int a = 0; a < 4; a++) {
        bfly(v[a][0], v[a][1], v[a][2], v[a][3]);
        tw3(v[a][1], v[a][2], v[a][3], w);
    }
}

// Pass B: stages m=256, m=64. element e(a,b) = u*1024 + rp + 64b + 256a
__device__ __forceinline__ void passB_fwd(float2* sA, const float2* sT, int t) {
    const int u = t >> 6, rp = t & 63;
    const int base = u * 1024 + rp;
    float2 v[4][4];
    #pragma unroll
    for (int a = 0; a < 4; a++)
        #pragma unroll
        for (int b = 0; b < 4; b++)
            v[a][b] = sA[SWZ(base + 64 * b + 256 * a)];
    #pragma unroll
    for (int b = 0; b < 4; b++) {
        bfly(v[0][b], v[1][b], v[2][b], v[3][b]);
        tw3(v[1][b], v[2][b], v[3][b], sT[OT256 + rp + 64 * b]);
    }
    float2 w = sT[OT64 + rp];
    #pragma unroll
    for (int a = 0; a < 4; a++) {
        bfly(v[a][0], v[a][1], v[a][2], v[a][3]);
        tw3(v[a][1], v[a][2], v[a][3], w);
    }
    #pragma unroll
    for (int a = 0; a < 4; a++)
        #pragma unroll
        for (int b = 0; b < 4; b++)
            sA[SWZ(base + 64 * b + 256 * a)] = v[a][b];
}

// Pass C: stage m=16. element e(s,a) = qb*64 + rq + 4096s + 16a
__device__ __forceinline__ void passC_fwd(float2* sA, const float2* sT, int t) {
    const int rq = t & 15, qb = t >> 4;
    const int base = qb * 64 + rq;
    float2 v[4][4];
    #pragma unroll
    for (int s = 0; s < 4; s++)
        #pragma unroll
        for (int a = 0; a < 4; a++)
            v[s][a] = sA[SWZ(base + 4096 * s + 16 * a)];
    float2 w = sT[OT16 + rq];
    #pragma unroll
    for (int s = 0; s < 4; s++) {
        bfly(v[s][0], v[s][1], v[s][2], v[s][3]);
        tw3(v[s][1], v[s][2], v[s][3], w);
    }
    #pragma unroll
    for (int s = 0; s < 4; s++)
        #pragma unroll
        for (int a = 0; a < 4; a++)
            sA[SWZ(base + 4096 * s + 16 * a)] = v[s][a];
}

// Pass D forward only: stages m=4, m=1 on u16 (elements 16t..16t+15)
__device__ __forceinline__ void passD_fwd(float2 u16[16], const float2* sT) {
    #pragma unroll
    for (int r = 0; r < 4; r++) {
        bfly(u16[r], u16[r + 4], u16[r + 8], u16[r + 12]);
        tw3(u16[r + 4], u16[r + 8], u16[r + 12], sT[OT4 + r]);
    }
    #pragma unroll
    for (int g = 0; g < 4; g++)
        bfly(u16[4 * g], u16[4 * g + 1], u16[4 * g + 2], u16[4 * g + 3]);
}

// ================= FFT of h: forward only, store spectrum ===================
__global__ __launch_bounds__(NT, 1)
void fft_h_kernel() {
    extern __shared__ float2 sm[];
    float2* sA = sm;
    float2* sT = sm + NFFT;
    const int t = threadIdx.x, d = blockIdx.x;

    for (int j = t; j < NTW; j += NT) sT[j] = g_twst[j];

    const float* hp = g_ht + (size_t)d * DIML;
    float2 v[4][4];
    #pragma unroll
    for (int a = 0; a < 4; a++)
        #pragma unroll
        for (int b = 0; b < 4; b++)
            v[a][b] = (a < 2) ? make_float2(hp[t + 1024 * b + 4096 * a], 0.0f)
                              : make_float2(0.0f, 0.0f);
    __syncthreads();                       // twiddle tables visible

    passA_fwd(v, sT, t);
    #pragma unroll
    for (int a = 0; a < 4; a++)
        #pragma unroll
        for (int b = 0; b < 4; b++)
            sA[SWZ(t + 1024 * b + 4096 * a)] = v[a][b];
    __syncthreads();

    passB_fwd(sA, sT, t);
    __syncthreads();
    passC_fwd(sA, sT, t);
    __syncthreads();

    float2 u16[16];
    #pragma unroll
    for (int j = 0; j < 16; j++) u16[j] = sA[SWZ(16 * t + j)];
    passD_fwd(u16, sT);

    float4* Hd = g_H + (size_t)d * (NFFT / 2) + 8 * t;
    #pragma unroll
    for (int p = 0; p < 8; p++)
        Hd[p] = make_float4(u16[2 * p].x, u16[2 * p].y, u16[2 * p + 1].x, u16[2 * p + 1].y);
}

// ================= conv: fwd FFT, multiply, inverse FFT =====================
__global__ __launch_bounds__(NT, 1)
void fft_conv_kernel() {
    extern __shared__ float2 sm[];
    float2* sA = sm;
    float2* sT = sm + NFFT;
    const int t = threadIdx.x, d = blockIdx.x;

    for (int j = t; j < NTW; j += NT) sT[j] = g_twst[j];

    const float2* xp = g_xt + (size_t)d * DIML;
    float2 v[4][4];
    #pragma unroll
    for (int a = 0; a < 4; a++)
        #pragma unroll
        for (int b = 0; b < 4; b++)
            v[a][b] = (a < 2) ? xp[t + 1024 * b + 4096 * a] : make_float2(0.0f, 0.0f);
    __syncthreads();

    passA_fwd(v, sT, t);
    #pragma unroll
    for (int a = 0; a < 4; a++)
        #pragma unroll
        for (int b = 0; b < 4; b++)
            sA[SWZ(t + 1024 * b + 4096 * a)] = v[a][b];
    __syncthreads();

    passB_fwd(sA, sT, t);
    __syncthreads();
    passC_fwd(sA, sT, t);
    __syncthreads();

    // ---- pass D: fwd(4,1) + multiply by H + inv(1,4), all in registers ----
    {
        float2 u16[16];
        #pragma unroll
        for (int j = 0; j < 16; j++) u16[j] = sA[SWZ(16 * t + j)];
        passD_fwd(u16, sT);

        const float4* Hd = g_H + (size_t)d * (NFFT / 2) + 8 * t;
        #pragma unroll
        for (int p = 0; p < 8; p++) {
            float4 hv = __ldg(&Hd[p]);
            u16[2 * p]     = cmul(u16[2 * p],     make_float2(hv.x, hv.y));
            u16[2 * p + 1] = cmul(u16[2 * p + 1], make_float2(hv.z, hv.w));
        }

        // inverse stage 1 then stage 4
        #pragma unroll
        for (int g = 0; g < 4; g++)
            ibfly(u16[4 * g], u16[4 * g + 1], u16[4 * g + 2], u16[4 * g + 3]);
        #pragma unroll
        for (int r = 0; r < 4; r++) {
            itw3(u16[r + 4], u16[r + 8], u16[r + 12], sT[OT4 + r]);
            ibfly(u16[r], u16[r + 4], u16[r + 8], u16[r + 12]);
        }
        #pragma unroll
        for (int j = 0; j < 16; j++) sA[SWZ(16 * t + j)] = u16[j];
    }
    __syncthreads();

    // ---- pass C': inverse stage 16 ----
    {
        const int rq = t & 15, qb = t >> 4;
        const int base = qb * 64 + rq;
        float2 w = sT[OT16 + rq];
        float2 vc[4][4];
        #pragma unroll
        for (int s = 0; s < 4; s++)
            #pragma unroll
            for (int a = 0; a < 4; a++)
                vc[s][a] = sA[SWZ(base + 4096 * s + 16 * a)];
        #pragma unroll
        for (int s = 0; s < 4; s++) {
            itw3(vc[s][1], vc[s][2], vc[s][3], w);
            ibfly(vc[s][0], vc[s][1], vc[s][2], vc[s][3]);
        }
        #pragma unroll
        for (int s = 0; s < 4; s++)
            #pragma unroll
            for (int a = 0; a < 4; a++)
                sA[SWZ(base + 4096 * s + 16 * a)] = vc[s][a];
    }
    __syncthreads();

    // ---- pass B': inverse stages 64 then 256 ----
    {
        const int u = t >> 6, rp = t & 63;
        const int base = u * 1024 + rp;
        float2 vb[4][4];
        #pragma unroll
        for (int a = 0; a < 4; a++)
            #pragma unroll
            for (int b = 0; b < 4; b++)
                vb[a][b] = sA[SWZ(base + 64 * b + 256 * a)];
        float2 w64 = sT[OT64 + rp];
        #pragma unroll
        for (int a = 0; a < 4; a++) {
            itw3(vb[a][1], vb[a][2], vb[a][3], w64);
            ibfly(vb[a][0], vb[a][1], vb[a][2], vb[a][3]);
        }
        #pragma unroll
        for (int b = 0; b < 4; b++) {
            itw3(vb[1][b], vb[2][b], vb[3][b], sT[OT256 + rp + 64 * b]);
            ibfly(vb[0][b], vb[1][b], vb[2][b], vb[3][b]);
        }
        #pragma unroll
        for (int a = 0; a < 4; a++)
            #pragma unroll
            for (int b = 0; b < 4; b++)
                sA[SWZ(base + 64 * b + 256 * a)] = vb[a][b];
    }
    __syncthreads();

    // ---- pass A': inverse stages 1024 then 4096, scale + store ----
    {
        float2 va[4][4];
        #pragma unroll
        for (int a = 0; a < 4; a++)
            #pragma unroll
            for (int b = 0; b < 4; b++)
                va[a][b] = sA[SWZ(t + 1024 * b + 4096 * a)];
        float2 w1024 = sT[OT1024 + t];
        #pragma unroll
        for (int a = 0; a < 4; a++) {
            itw3(va[a][1], va[a][2], va[a][3], w1024);
            ibfly(va[a][0], va[a][1], va[a][2], va[a][3]);
        }
        #pragma unroll
        for (int b = 0; b < 4; b++) {
            itw3(va[1][b], va[2][b], va[3][b], sT[OT4096 + t + 1024 * b]);
            ibfly(va[0][b], va[1][b], va[2][b], va[3][b]);
        }
        const float scale = 1.0f / (float)NFFT;
        float2* yp = g_ys + (size_t)d * DIML;
        #pragma unroll
        for (int a = 0; a < 2; a++)
            #pragma unroll
            for (int b = 0; b < 4; b++) {
                float2 r = va[a][b];
                yp[t + 1024 * b + 4096 * a] = make_float2(r.x * scale, r.y * scale);
            }
    }
}

// ---------------------------------------------------------------------------
extern "C" void kernel_launch(void* const* d_in, const int* in_sizes, int n_in,
                              void* d_out, int out_size) {
    const float* x    = (const float*)d_in[0];
    const float* h    = (const float*)d_in[1];
    const float* bias = (const float*)d_in[2];
    float* y = (float*)d_out;

    const int smem = (NFFT + NTW) * sizeof(float2);  // ~171 KB
    cudaFuncSetAttribute(fft_h_kernel,
                         cudaFuncAttributeMaxDynamicSharedMemorySize, smem);
    cudaFuncSetAttribute(fft_conv_kernel,
                         cudaFuncAttributeMaxDynamicSharedMemorySize, smem);

    twiddle_kernel<<<dim3(16, 6), 256>>>();
    transpose_x_kernel<<<dim3(DIMD / 32, DIML / 32), dim3(32, 8)>>>(x);
    transpose_h_kernel<<<dim3(DIMD / 32, DIML / 32), dim3(32, 8)>>>(h);
    fft_h_kernel<<<DIMD, NT, smem>>>();
    fft_conv_kernel<<<DIMD, NT, smem>>>();
    transpose_out_kernel<<<dim3(DIML / 32, DIMD / 32), dim3(32, 8)>>>(bias, y);
}